// round 14
// baseline (speedup 1.0000x reference)
#include <cuda_runtime.h>
#include <math.h>

// Problem dims
#define BB 2
#define SS 2048
#define DD 1024
#define HH 16
#define HD 64
#define ROWS (BB*SS)          // 4096
#define EPS 1e-6f

typedef unsigned long long u64;

// ---------------- packed f32x2 helpers (sm_103a FFMA2 pipe) ----------------
__device__ __forceinline__ u64 fma2(u64 a, u64 b, u64 c) {
    u64 d;
    asm("fma.rn.f32x2 %0, %1, %2, %3;" : "=l"(d) : "l"(a), "l"(b), "l"(c));
    return d;
}
__device__ __forceinline__ u64 mul2(u64 a, u64 b) {
    u64 d;
    asm("mul.rn.f32x2 %0, %1, %2;" : "=l"(d) : "l"(a), "l"(b));
    return d;
}
__device__ __forceinline__ u64 pack2(float lo, float hi) {
    u64 d;
    asm("mov.b64 %0, {%1, %2};" : "=l"(d) : "f"(lo), "f"(hi));
    return d;
}
__device__ __forceinline__ float lo2(u64 a) { return __uint_as_float((unsigned)a); }
__device__ __forceinline__ float hi2(u64 a) { return __uint_as_float((unsigned)(a >> 32)); }
__device__ __forceinline__ float ex2(float x) {
    float r;
    asm("ex2.approx.f32 %0, %1;" : "=f"(r) : "f"(x));
    return r;
}

// ---------------- tf32 mma helpers -----------------------------------------
__device__ __forceinline__ float cvt_tf32(float x) {
    float r;
    asm("cvt.rna.tf32.f32 %0, %1;" : "=f"(r) : "f"(x));
    return r;
}
__device__ __forceinline__ void mma_tf32(
    float& c0, float& c1, float& c2, float& c3,
    unsigned a0, unsigned a1, unsigned a2, unsigned a3,
    unsigned b0, unsigned b1)
{
    asm volatile(
        "mma.sync.aligned.m16n8k8.row.col.f32.tf32.tf32.f32 "
        "{%0,%1,%2,%3}, {%4,%5,%6,%7}, {%8,%9}, {%0,%1,%2,%3};"
        : "+f"(c0), "+f"(c1), "+f"(c2), "+f"(c3)
        : "r"(a0), "r"(a1), "r"(a2), "r"(a3), "r"(b0), "r"(b1));
}

// ---------------- scratch (device globals; no allocation allowed) ----------
__device__ float g_xn  [ROWS * DD];
__device__ float g_qkv [ROWS * 3 * DD];
__device__ float g_q   [BB * HH * SS * HD];  // [b,h,s,d]
__device__ float g_k   [BB * HH * SS * HD];
__device__ float g_v   [BB * HH * SS * HD];
__device__ float g_attn[ROWS * DD];          // [b,s,h*64+d]

// ---------------- kernel 1: row LayerNorm over D=1024 ---------------------
__global__ __launch_bounds__(256) void ln_kernel(
    const float* __restrict__ x, const float* __restrict__ scale,
    const float* __restrict__ bias, float* __restrict__ y)
{
    __shared__ float sh[8];
    const int t = threadIdx.x;
    const size_t row = blockIdx.x;
    const float* xr = x + row * DD;

    float v0 = xr[t], v1 = xr[t + 256], v2 = xr[t + 512], v3 = xr[t + 768];

    float s = v0 + v1 + v2 + v3;
    #pragma unroll
    for (int o = 16; o; o >>= 1) s += __shfl_xor_sync(0xffffffffu, s, o);
    if ((t & 31) == 0) sh[t >> 5] = s;
    __syncthreads();
    float tot = 0.f;
    #pragma unroll
    for (int i = 0; i < 8; i++) tot += sh[i];
    const float mean = tot * (1.f / 1024.f);

    float a0 = v0 - mean, a1 = v1 - mean, a2 = v2 - mean, a3 = v3 - mean;
    float sq = a0*a0 + a1*a1 + a2*a2 + a3*a3;
    #pragma unroll
    for (int o = 16; o; o >>= 1) sq += __shfl_xor_sync(0xffffffffu, sq, o);
    __syncthreads();
    if ((t & 31) == 0) sh[t >> 5] = sq;
    __syncthreads();
    float tsq = 0.f;
    #pragma unroll
    for (int i = 0; i < 8; i++) tsq += sh[i];
    const float rstd = rsqrtf(tsq * (1.f / 1024.f) + EPS);

    float* yr = y + row * DD;
    yr[t      ] = a0 * rstd * scale[t      ] + bias[t      ];
    yr[t + 256] = a1 * rstd * scale[t + 256] + bias[t + 256];
    yr[t + 512] = a2 * rstd * scale[t + 512] + bias[t + 512];
    yr[t + 768] = a3 * rstd * scale[t + 768] + bias[t + 768];
}

// ---------------- kernel 2: 3xTF32 tensor-core GEMM + bias (EXACT R11) ----
#define GKT 16
__global__ __launch_bounds__(256) void sgemm_tf32(
    const float* __restrict__ A, const float* __restrict__ B,
    const float* __restrict__ bias, float* __restrict__ C,
    int M, int N, int K)
{
    __shared__ float AsH[GKT][136], AsL[GKT][136];
    __shared__ float BsH[GKT][136], BsL[GKT][136];

    const int tid = threadIdx.x;
    const int wid = tid >> 5;
    const int lane = tid & 31;
    const int g = lane >> 2;          // 0..7
    const int t = lane & 3;           // 0..3
    const int warp_m = wid >> 2;      // 0..1
    const int warp_n = wid & 3;       // 0..3
    const int rowBase = blockIdx.y * 128;
    const int colBase = blockIdx.x * 128;

    const int am = tid >> 1;              // 0..127 (A row within tile)
    const int ak = (tid & 1) * 8;         // 0 or 8 (A k-offset)
    const int bk = tid >> 4;              // 0..15  (B k-row)
    const int bn = (tid & 15) * 8;        // 0..120 (B n-offset)

    float c[4][4][4];
    #pragma unroll
    for (int mi = 0; mi < 4; mi++)
        #pragma unroll
        for (int ni = 0; ni < 4; ni++)
            #pragma unroll
            for (int e = 0; e < 4; e++) c[mi][ni][e] = 0.f;

    for (int k0 = 0; k0 < K; k0 += GKT) {
        __syncthreads();
        // ---- fill A (transposed into k-major rows, split hi/lo) ----
        #pragma unroll
        for (int q = 0; q < 2; q++) {
            const int kk = ak + q * 4;
            float4 v = *(const float4*)(A + (size_t)(rowBase + am) * K + k0 + kk);
            float h;
            h = cvt_tf32(v.x); AsH[kk + 0][am] = h; AsL[kk + 0][am] = v.x - h;
            h = cvt_tf32(v.y); AsH[kk + 1][am] = h; AsL[kk + 1][am] = v.y - h;
            h = cvt_tf32(v.z); AsH[kk + 2][am] = h; AsL[kk + 2][am] = v.z - h;
            h = cvt_tf32(v.w); AsH[kk + 3][am] = h; AsL[kk + 3][am] = v.w - h;
        }
        // ---- fill B (natural k x n, split hi/lo, vectorized stores) ----
        #pragma unroll
        for (int q = 0; q < 2; q++) {
            const int nn = bn + q * 4;
            float4 v = *(const float4*)(B + (size_t)(k0 + bk) * N + colBase + nn);
            float4 hh, ll;
            hh.x = cvt_tf32(v.x); ll.x = v.x - hh.x;
            hh.y = cvt_tf32(v.y); ll.y = v.y - hh.y;
            hh.z = cvt_tf32(v.z); ll.z = v.z - hh.z;
            hh.w = cvt_tf32(v.w); ll.w = v.w - hh.w;
            *(float4*)&BsH[bk][nn] = hh;
            *(float4*)&BsL[bk][nn] = ll;
        }
        __syncthreads();

        #pragma unroll
        for (int ks = 0; ks < GKT; ks += 8) {
            unsigned aH[4][4], aL[4][4], bH[4][2], bL[4][2];
            #pragma unroll
            for (int mi = 0; mi < 4; mi++) {
                const int r = warp_m * 64 + mi * 16 + g;
                aH[mi][0] = __float_as_uint(AsH[ks + t    ][r    ]);
                aH[mi][1] = __float_as_uint(AsH[ks + t    ][r + 8]);
                aH[mi][2] = __float_as_uint(AsH[ks + t + 4][r    ]);
                aH[mi][3] = __float_as_uint(AsH[ks + t + 4][r + 8]);
                aL[mi][0] = __float_as_uint(AsL[ks + t    ][r    ]);
                aL[mi][1] = __float_as_uint(AsL[ks + t    ][r + 8]);
                aL[mi][2] = __float_as_uint(AsL[ks + t + 4][r    ]);
                aL[mi][3] = __float_as_uint(AsL[ks + t + 4][r + 8]);
            }
            #pragma unroll
            for (int ni = 0; ni < 4; ni++) {
                const int n = warp_n * 32 + ni * 8 + g;
                bH[ni][0] = __float_as_uint(BsH[ks + t    ][n]);
                bH[ni][1] = __float_as_uint(BsH[ks + t + 4][n]);
                bL[ni][0] = __float_as_uint(BsL[ks + t    ][n]);
                bL[ni][1] = __float_as_uint(BsL[ks + t + 4][n]);
            }
            #pragma unroll
            for (int mi = 0; mi < 4; mi++)
                #pragma unroll
                for (int ni = 0; ni < 4; ni++)
                    mma_tf32(c[mi][ni][0], c[mi][ni][1], c[mi][ni][2], c[mi][ni][3],
                             aH[mi][0], aH[mi][1], aH[mi][2], aH[mi][3],
                             bH[ni][0], bH[ni][1]);
            #pragma unroll
            for (int mi = 0; mi < 4; mi++)
                #pragma unroll
                for (int ni = 0; ni < 4; ni++)
                    mma_tf32(c[mi][ni][0], c[mi][ni][1], c[mi][ni][2], c[mi][ni][3],
                             aH[mi][0], aH[mi][1], aH[mi][2], aH[mi][3],
                             bL[ni][0], bL[ni][1]);
            #pragma unroll
            for (int mi = 0; mi < 4; mi++)
                #pragma unroll
                for (int ni = 0; ni < 4; ni++)
                    mma_tf32(c[mi][ni][0], c[mi][ni][1], c[mi][ni][2], c[mi][ni][3],
                             aL[mi][0], aL[mi][1], aL[mi][2], aL[mi][3],
                             bH[ni][0], bH[ni][1]);
        }
    }

    // ---- epilogue: bias + store ----
    #pragma unroll
    for (int ni = 0; ni < 4; ni++) {
        const int col = colBase + warp_n * 32 + ni * 8 + 2 * t;
        const float2 bb = *(const float2*)(bias + col);
        #pragma unroll
        for (int mi = 0; mi < 4; mi++) {
            const int row = rowBase + warp_m * 64 + mi * 16 + g;
            float2 o0, o1;
            o0.x = c[mi][ni][0] + bb.x;  o0.y = c[mi][ni][1] + bb.y;
            o1.x = c[mi][ni][2] + bb.x;  o1.y = c[mi][ni][3] + bb.y;
            *(float2*)(C + (size_t)row * N + col)       = o0;
            *(float2*)(C + (size_t)(row + 8) * N + col) = o1;
        }
    }
}

// ---------------- kernel 3: per-head LN (q,k) + RoPE + transpose ----------
__global__ __launch_bounds__(128) void qk_rope_kernel(
    const float* __restrict__ qkv,
    const float* __restrict__ q_scale, const float* __restrict__ k_scale,
    float* __restrict__ Q, float* __restrict__ K, float* __restrict__ V)
{
    const int w = blockIdx.x * 4 + (threadIdx.x >> 5);
    const int lane = threadIdx.x & 31;
    const int h = w % HH;
    const int s = (w / HH) % SS;
    const int b = w / (HH * SS);

    const float* row = qkv + (size_t)(b * SS + s) * (3 * DD) + h * HD;
    float q0 = row[lane],        q1 = row[lane + 32];
    float k0 = row[DD + lane],   k1 = row[DD + lane + 32];
    float v0 = row[2*DD + lane], v1 = row[2*DD + lane + 32];

    float mu = q0 + q1;
    #pragma unroll
    for (int o = 16; o; o >>= 1) mu += __shfl_xor_sync(0xffffffffu, mu, o);
    mu *= (1.f / 64.f);
    float a0 = q0 - mu, a1 = q1 - mu;
    float var = a0 * a0 + a1 * a1;
    #pragma unroll
    for (int o = 16; o; o >>= 1) var += __shfl_xor_sync(0xffffffffu, var, o);
    float r = rsqrtf(var * (1.f / 64.f) + EPS);
    float yq0 = a0 * r * q_scale[lane], yq1 = a1 * r * q_scale[lane + 32];

    mu = k0 + k1;
    #pragma unroll
    for (int o = 16; o; o >>= 1) mu += __shfl_xor_sync(0xffffffffu, mu, o);
    mu *= (1.f / 64.f);
    a0 = k0 - mu; a1 = k1 - mu;
    var = a0 * a0 + a1 * a1;
    #pragma unroll
    for (int o = 16; o; o >>= 1) var += __shfl_xor_sync(0xffffffffu, var, o);
    r = rsqrtf(var * (1.f / 64.f) + EPS);
    float yk0 = a0 * r * k_scale[lane], yk1 = a1 * r * k_scale[lane + 32];

    const float invf = (float)exp(-(double)(2 * lane) / 64.0 * log(10000.0));
    const float ang = (float)s * invf;
    const float c = cosf(ang), sn = sinf(ang);

    float oq0 = yq0 * c - yq1 * sn;
    float oq1 = yq1 * c + yq0 * sn;
    float ok0 = yk0 * c - yk1 * sn;
    float ok1 = yk1 * c + yk0 * sn;

    const size_t base = ((size_t)(b * HH + h) * SS + s) * HD;
    Q[base + lane] = oq0; Q[base + lane + 32] = oq1;
    K[base + lane] = ok0; K[base + lane + 32] = ok1;
    V[base + lane] = v0;  V[base + lane + 32] = v1;
}

// ---------------- kernel 4: flash attention v6 (quarter-split, 3 blk/SM) ---
// tid = 4m + h: m in [0,32) query-pair index; h in [0,4) owns dims
// [16h, 16h+16). Thread handles queries q0+m and q0+32+m (64-query tiles).
// ~160 regs -> 3 blocks/SM = 12 warps (was 8). Smem: row stride 20 ull2,
// quarter h at h*5 ull2 -> read addrs mod 8 = {0,5,2,7}: 1 wavefront/LDS.128.
// Softmax: 8-key batch, 2-level shfl_xor (1 then 2). No online max (scores
// bounded in [-8,8] post-LN, proven R7-R13).
#define FQ_ROW 20   // ull2 stride per key row
__global__ __launch_bounds__(128, 3) void flash_kernel(
    const float* __restrict__ Q, const float* __restrict__ K,
    const float* __restrict__ V, float* __restrict__ O)
{
    __shared__ ulonglong2 Ks2[64 * FQ_ROW];   // 20480 B
    __shared__ ulonglong2 Vs2[64 * FQ_ROW];   // 20480 B

    const int tid = threadIdx.x;
    const int m = tid >> 2;        // 0..31
    const int h = tid & 3;         // quarter
    const int bh = blockIdx.y;     // 0..31
    const int q0 = blockIdx.x * 64;
    const int rA = q0 + m;
    const int rB = q0 + 32 + m;

    const float QSCALE = 0.125f * 1.44269504088896340736f;  // /sqrt(64)*log2(e)
    const u64 qsc = pack2(QSCALE, QSCALE);

    // load this thread's quarter of both query rows, pre-scaled
    u64 qA[8], qB[8];
    {
        const ulonglong2* Qa = (const ulonglong2*)(Q + ((size_t)bh * SS + rA) * HD + h * 16);
        const ulonglong2* Qb = (const ulonglong2*)(Q + ((size_t)bh * SS + rB) * HD + h * 16);
        #pragma unroll
        for (int i = 0; i < 4; i++) {
            ulonglong2 ta = Qa[i];
            qA[2*i] = mul2(ta.x, qsc); qA[2*i+1] = mul2(ta.y, qsc);
            ulonglong2 tb = Qb[i];
            qB[2*i] = mul2(tb.x, qsc); qB[2*i+1] = mul2(tb.y, qsc);
        }
    }

    u64 accA[8], accB[8];
    #pragma unroll
    for (int i = 0; i < 8; i++) { accA[i] = 0ull; accB[i] = 0ull; }
    float la = 0.f, lb = 0.f;

    for (int kt = 0; kt < SS / 64; kt++) {
        const ulonglong2* Kg = (const ulonglong2*)(K + ((size_t)bh * SS + kt * 64) * HD);
        const ulonglong2* Vg = (const ulonglong2*)(V + ((size_t)bh * SS + kt * 64) * HD);
        __syncthreads();
        #pragma unroll
        for (int i = 0; i < 8; i++) {
            const int e  = tid + i * 128;        // 0..1023
            const int j  = e >> 4;
            const int qq = e & 15;
            const int di = j * FQ_ROW + (qq >> 2) * 5 + (qq & 3);
            Ks2[di] = Kg[e];
            Vs2[di] = Vg[e];
        }
        __syncthreads();

        const ulonglong2* Ksh = Ks2 + h * 5;
        const ulonglong2* Vsh = Vs2 + h * 5;

        #pragma unroll 1
        for (int jt = 0; jt < 64; jt += 8) {
            // ---- phase 1: score partials for 8 keys (16 indep chains) ----
            u64 cA[8], cB[8];
            #pragma unroll
            for (int j = 0; j < 8; j++) {
                const ulonglong2* kr = Ksh + (jt + j) * FQ_ROW;
                u64 a = 0ull, b = 0ull;
                #pragma unroll
                for (int k4 = 0; k4 < 4; k4++) {
                    ulonglong2 kk = kr[k4];
                    a = fma2(qA[2*k4  ], kk.x, a);
                    a = fma2(qA[2*k4+1], kk.y, a);
                    b = fma2(qB[2*k4  ], kk.x, b);
                    b = fma2(qB[2*k4+1], kk.y, b);
                }
                cA[j] = a; cB[j] = b;
            }

            // ---- phase 2: batched combine (2-level) + exp ----
            float pA[8], pB[8];
            #pragma unroll
            for (int j = 0; j < 8; j++) {
                float sa = lo2(cA[j]) + hi2(cA[j]);
                float sb = lo2(cB[j]) + hi2(cB[j]);
                sa += __shfl_xor_sync(0xffffffffu, sa, 1);
                sb += __shfl_xor_sync(0xffffffffu, sb, 1);
                sa += __shfl_xor_sync(0xffffffffu, sa, 2);
                sb += __shfl_xor_sync(0xffffffffu, sb, 2);
                pA[j] = ex2(sa);
                pB[j] = ex2(sb);
            }
            #pragma unroll
            for (int j = 0; j < 8; j++) { la += pA[j]; lb += pB[j]; }

            // ---- phase 3: PV for the 8 keys (this thread's quarter) ----
            #pragma unroll
            for (int j = 0; j < 8; j++) {
                const ulonglong2* vr = Vsh + (jt + j) * FQ_ROW;
                const u64 ppa = pack2(pA[j], pA[j]);
                const u64 ppb = pack2(pB[j], pB[j]);
                #pragma unroll
                for (int d4 = 0; d4 < 4; d4++) {
                    ulonglong2 vv = vr[d4];
                    accA[2*d4  ] = fma2(ppa, vv.x, accA[2*d4  ]);
                    accA[2*d4+1] = fma2(ppa, vv.y, accA[2*d4+1]);
                    accB[2*d4  ] = fma2(ppb, vv.x, accB[2*d4  ]);
                    accB[2*d4+1] = fma2(ppb, vv.y, accB[2*d4+1]);
                }
            }
        }
    }

    const int b = bh >> 4, hh = bh & 15;
    const u64 pia = pack2(1.f / la, 1.f / la);
    const u64 pib = pack2(1.f / lb, 1.f / lb);
    ulonglong2* Oa = (ulonglong2*)(O + ((size_t)(b * SS + rA)) * DD + hh * HD + h * 16);
    ulonglong2* Ob = (ulonglong2*)(O + ((size_t)(b * SS + rB)) * DD + hh * HD + h * 16);
    #pragma unroll
    for (int i = 0; i < 4; i++) {
        ulonglong2 ta, tb;
        ta.x = mul2(accA[2*i], pia); ta.y = mul2(accA[2*i+1], pia);
        tb.x = mul2(accB[2*i], pib); tb.y = mul2(accB[2*i+1], pib);
        Oa[i] = ta;
        Ob[i] = tb;
    }
}

// ---------------- launcher -------------------------------------------------
extern "C" void kernel_launch(void* const* d_in, const int* in_sizes, int n_in,
                              void* d_out, int out_size)
{
    const float* x        = (const float*)d_in[0];
    const float* w_qkv    = (const float*)d_in[1];
    const float* b_qkv    = (const float*)d_in[2];
    const float* w_out    = (const float*)d_in[3];
    const float* b_out    = (const float*)d_in[4];
    const float* ln_scale = (const float*)d_in[5];
    const float* ln_bias  = (const float*)d_in[6];
    const float* q_scale  = (const float*)d_in[7];
    const float* k_scale  = (const float*)d_in[8];
    float* out = (float*)d_out;

    float *xn, *qkv, *q, *k, *v, *attn;
    cudaGetSymbolAddress((void**)&xn,   g_xn);
    cudaGetSymbolAddress((void**)&qkv,  g_qkv);
    cudaGetSymbolAddress((void**)&q,    g_q);
    cudaGetSymbolAddress((void**)&k,    g_k);
    cudaGetSymbolAddress((void**)&v,    g_v);
    cudaGetSymbolAddress((void**)&attn, g_attn);

    // 1) input layernorm
    ln_kernel<<<ROWS, 256>>>(x, ln_scale, ln_bias, xn);

    // 2) QKV projection: [4096,1024] @ [1024,3072]  (3xTF32, exact R11)
    sgemm_tf32<<<dim3(3 * DD / 128, ROWS / 128), 256>>>(xn, w_qkv, b_qkv, qkv,
                                                        ROWS, 3 * DD, DD);

    // 3) head LN + RoPE + layout change
    qk_rope_kernel<<<(BB * SS * HH) / 4, 128>>>(qkv, q_scale, k_scale, q, k, v);

    // 4) attention: quarter-split, 64-query tiles, 3 blocks/SM
    flash_kernel<<<dim3(SS / 64, BB * HH), 128>>>(q, k, v, attn);

    // 5) output projection: [4096,1024] @ [1024,1024]  (3xTF32, exact R11)
    sgemm_tf32<<<dim3(DD / 128, ROWS / 128), 256>>>(attn, w_out, b_out, out,
                                                    ROWS, DD, DD);
}

// round 15
// speedup vs baseline: 1.4428x; 1.4428x over previous
#include <cuda_runtime.h>
#include <cuda_bf16.h>
#include <math.h>

// Problem dims
#define BB 2
#define SS 2048
#define DD 1024
#define HH 16
#define HD 64
#define ROWS (BB*SS)          // 4096
#define EPS 1e-6f

typedef unsigned long long u64;

// ---------------- packed f32x2 helpers (sm_103a FFMA2 pipe) ----------------
__device__ __forceinline__ u64 fma2(u64 a, u64 b, u64 c) {
    u64 d;
    asm("fma.rn.f32x2 %0, %1, %2, %3;" : "=l"(d) : "l"(a), "l"(b), "l"(c));
    return d;
}
__device__ __forceinline__ u64 mul2(u64 a, u64 b) {
    u64 d;
    asm("mul.rn.f32x2 %0, %1, %2;" : "=l"(d) : "l"(a), "l"(b));
    return d;
}
__device__ __forceinline__ u64 pack2(float lo, float hi) {
    u64 d;
    asm("mov.b64 %0, {%1, %2};" : "=l"(d) : "f"(lo), "f"(hi));
    return d;
}
__device__ __forceinline__ float lo2(u64 a) { return __uint_as_float((unsigned)a); }
__device__ __forceinline__ float hi2(u64 a) { return __uint_as_float((unsigned)(a >> 32)); }
__device__ __forceinline__ float ex2(float x) {
    float r;
    asm("ex2.approx.f32 %0, %1;" : "=f"(r) : "f"(x));
    return r;
}

// ---------------- bf16 mma helpers -----------------------------------------
// split x = hi + lo, both bf16; missing ll-term error ~2^-16 per product.
__device__ __forceinline__ void bf16split(float x, unsigned short& h, unsigned short& l) {
    __nv_bfloat16 bh = __float2bfloat16_rn(x);
    float res = x - __bfloat162float(bh);
    __nv_bfloat16 bl = __float2bfloat16_rn(res);
    h = __bfloat16_as_ushort(bh);
    l = __bfloat16_as_ushort(bl);
}
__device__ __forceinline__ unsigned packu(unsigned short lo16, unsigned short hi16) {
    return (unsigned)lo16 | ((unsigned)hi16 << 16);
}
__device__ __forceinline__ void mma_bf16(
    float& c0, float& c1, float& c2, float& c3,
    unsigned a0, unsigned a1, unsigned a2, unsigned a3,
    unsigned b0, unsigned b1)
{
    asm volatile(
        "mma.sync.aligned.m16n8k16.row.col.f32.bf16.bf16.f32 "
        "{%0,%1,%2,%3}, {%4,%5,%6,%7}, {%8,%9}, {%0,%1,%2,%3};"
        : "+f"(c0), "+f"(c1), "+f"(c2), "+f"(c3)
        : "r"(a0), "r"(a1), "r"(a2), "r"(a3), "r"(b0), "r"(b1));
}

// ---------------- scratch (device globals; no allocation allowed) ----------
__device__ float g_xn  [ROWS * DD];
__device__ float g_qkv [ROWS * 3 * DD];
__device__ float g_q   [BB * HH * SS * HD];  // [b,h,s,d]
__device__ float g_k   [BB * HH * SS * HD];
__device__ float g_v   [BB * HH * SS * HD];
__device__ float g_attn[ROWS * DD];          // [b,s,h*64+d]

// ---------------- kernel 1: row LayerNorm over D=1024 ---------------------
__global__ __launch_bounds__(256) void ln_kernel(
    const float* __restrict__ x, const float* __restrict__ scale,
    const float* __restrict__ bias, float* __restrict__ y)
{
    __shared__ float sh[8];
    const int t = threadIdx.x;
    const size_t row = blockIdx.x;
    const float* xr = x + row * DD;

    float v0 = xr[t], v1 = xr[t + 256], v2 = xr[t + 512], v3 = xr[t + 768];

    float s = v0 + v1 + v2 + v3;
    #pragma unroll
    for (int o = 16; o; o >>= 1) s += __shfl_xor_sync(0xffffffffu, s, o);
    if ((t & 31) == 0) sh[t >> 5] = s;
    __syncthreads();
    float tot = 0.f;
    #pragma unroll
    for (int i = 0; i < 8; i++) tot += sh[i];
    const float mean = tot * (1.f / 1024.f);

    float a0 = v0 - mean, a1 = v1 - mean, a2 = v2 - mean, a3 = v3 - mean;
    float sq = a0*a0 + a1*a1 + a2*a2 + a3*a3;
    #pragma unroll
    for (int o = 16; o; o >>= 1) sq += __shfl_xor_sync(0xffffffffu, sq, o);
    __syncthreads();
    if ((t & 31) == 0) sh[t >> 5] = sq;
    __syncthreads();
    float tsq = 0.f;
    #pragma unroll
    for (int i = 0; i < 8; i++) tsq += sh[i];
    const float rstd = rsqrtf(tsq * (1.f / 1024.f) + EPS);

    float* yr = y + row * DD;
    yr[t      ] = a0 * rstd * scale[t      ] + bias[t      ];
    yr[t + 256] = a1 * rstd * scale[t + 256] + bias[t + 256];
    yr[t + 512] = a2 * rstd * scale[t + 512] + bias[t + 512];
    yr[t + 768] = a3 * rstd * scale[t + 768] + bias[t + 768];
}

// ---------------- kernel 2: 3-pass BF16 tensor-core GEMM + bias -----------
// Structure identical to the measured R11 tf32 kernel: 128x128 tile,
// 256 thr = 8 warps (2m x 4n), warp tile 64x32, [16][136] 32-bit smem words
// with the SAME fragment index expressions. Words now hold packed bf16
// (k, k+1) pairs, mma is m16n8k16.bf16 (2x MAC per instruction and per
// fragment LDS), K-tile = 32 (instruction mix per tile unchanged; half the
// tiles and syncs). Passes: hiA*hiB + hiA*loB + loA*hiB.
#define GKT 32
__global__ __launch_bounds__(256) void sgemm_bf16(
    const float* __restrict__ A, const float* __restrict__ B,
    const float* __restrict__ bias, float* __restrict__ C,
    int M, int N, int K)
{
    __shared__ unsigned AsH[16][136], AsL[16][136];   // kp-major, pair=(k,k+1)
    __shared__ unsigned BsH[16][136], BsL[16][136];

    const int tid = threadIdx.x;
    const int wid = tid >> 5;
    const int lane = tid & 31;
    const int g = lane >> 2;          // 0..7
    const int t = lane & 3;           // 0..3
    const int warp_m = wid >> 2;      // 0..1
    const int warp_n = wid & 3;       // 0..3
    const int rowBase = blockIdx.y * 128;
    const int colBase = blockIdx.x * 128;

    // A fill: thread loads row am, 16 consecutive k (ak = 0 or 16)
    const int am  = tid >> 1;             // 0..127
    const int ak  = (tid & 1) * 16;       // 0 or 16
    const int akp = ak >> 1;              // kp base 0 or 8
    // B fill: thread loads 2 k-rows (2*bkp, 2*bkp+1), 8 n-cols
    const int bkp = (tid >> 3) & 15;                        // 0..15
    const int bn  = (((tid & 7) | ((tid >> 7) << 3))) * 8;  // 0..120

    float c[4][4][4];
    #pragma unroll
    for (int mi = 0; mi < 4; mi++)
        #pragma unroll
        for (int ni = 0; ni < 4; ni++)
            #pragma unroll
            for (int e = 0; e < 4; e++) c[mi][ni][e] = 0.f;

    for (int k0 = 0; k0 < K; k0 += GKT) {
        __syncthreads();
        // ---- fill A: 16 floats -> 8 (hi,lo) kp pairs at column am ----
        {
            const float* Ap = A + (size_t)(rowBase + am) * K + k0 + ak;
            float4 v0 = *(const float4*)(Ap);
            float4 v1 = *(const float4*)(Ap + 4);
            float4 v2 = *(const float4*)(Ap + 8);
            float4 v3 = *(const float4*)(Ap + 12);
            float va[16] = {v0.x,v0.y,v0.z,v0.w, v1.x,v1.y,v1.z,v1.w,
                            v2.x,v2.y,v2.z,v2.w, v3.x,v3.y,v3.z,v3.w};
            #pragma unroll
            for (int p = 0; p < 8; p++) {
                unsigned short h0, l0, h1, l1;
                bf16split(va[2*p],     h0, l0);
                bf16split(va[2*p + 1], h1, l1);
                AsH[akp + p][am] = packu(h0, h1);   // low = even k
                AsL[akp + p][am] = packu(l0, l1);
            }
        }
        // ---- fill B: rows 2*bkp, 2*bkp+1, cols bn..bn+7 -> kp row bkp ----
        {
            const float* B0 = B + (size_t)(k0 + 2 * bkp) * N + colBase + bn;
            const float* B1 = B0 + N;
            float4 r0a = *(const float4*)(B0);
            float4 r0b = *(const float4*)(B0 + 4);
            float4 r1a = *(const float4*)(B1);
            float4 r1b = *(const float4*)(B1 + 4);
            float r0[8] = {r0a.x,r0a.y,r0a.z,r0a.w, r0b.x,r0b.y,r0b.z,r0b.w};
            float r1[8] = {r1a.x,r1a.y,r1a.z,r1a.w, r1b.x,r1b.y,r1b.z,r1b.w};
            unsigned hbuf[8], lbuf[8];
            #pragma unroll
            for (int j = 0; j < 8; j++) {
                unsigned short h0, l0, h1, l1;
                bf16split(r0[j], h0, l0);
                bf16split(r1[j], h1, l1);
                hbuf[j] = packu(h0, h1);            // low = even k row
                lbuf[j] = packu(l0, l1);
            }
            *(uint4*)&BsH[bkp][bn]     = make_uint4(hbuf[0], hbuf[1], hbuf[2], hbuf[3]);
            *(uint4*)&BsH[bkp][bn + 4] = make_uint4(hbuf[4], hbuf[5], hbuf[6], hbuf[7]);
            *(uint4*)&BsL[bkp][bn]     = make_uint4(lbuf[0], lbuf[1], lbuf[2], lbuf[3]);
            *(uint4*)&BsL[bkp][bn + 4] = make_uint4(lbuf[4], lbuf[5], lbuf[6], lbuf[7]);
        }
        __syncthreads();

        // ---- compute: two k16 chunks per tile (kp rows 0..7, 8..15) ----
        #pragma unroll
        for (int ks = 0; ks < 16; ks += 8) {
            unsigned aH[4][4], aL[4][4], bH[4][2], bL[4][2];
            #pragma unroll
            for (int mi = 0; mi < 4; mi++) {
                const int r = warp_m * 64 + mi * 16 + g;
                aH[mi][0] = AsH[ks + t    ][r    ];
                aH[mi][1] = AsH[ks + t    ][r + 8];
                aH[mi][2] = AsH[ks + t + 4][r    ];
                aH[mi][3] = AsH[ks + t + 4][r + 8];
                aL[mi][0] = AsL[ks + t    ][r    ];
                aL[mi][1] = AsL[ks + t    ][r + 8];
                aL[mi][2] = AsL[ks + t + 4][r    ];
                aL[mi][3] = AsL[ks + t + 4][r + 8];
            }
            #pragma unroll
            for (int ni = 0; ni < 4; ni++) {
                const int n = warp_n * 32 + ni * 8 + g;
                bH[ni][0] = BsH[ks + t    ][n];
                bH[ni][1] = BsH[ks + t + 4][n];
                bL[ni][0] = BsL[ks + t    ][n];
                bL[ni][1] = BsL[ks + t + 4][n];
            }
            #pragma unroll
            for (int mi = 0; mi < 4; mi++)
                #pragma unroll
                for (int ni = 0; ni < 4; ni++)
                    mma_bf16(c[mi][ni][0], c[mi][ni][1], c[mi][ni][2], c[mi][ni][3],
                             aH[mi][0], aH[mi][1], aH[mi][2], aH[mi][3],
                             bH[ni][0], bH[ni][1]);
            #pragma unroll
            for (int mi = 0; mi < 4; mi++)
                #pragma unroll
                for (int ni = 0; ni < 4; ni++)
                    mma_bf16(c[mi][ni][0], c[mi][ni][1], c[mi][ni][2], c[mi][ni][3],
                             aH[mi][0], aH[mi][1], aH[mi][2], aH[mi][3],
                             bL[ni][0], bL[ni][1]);
            #pragma unroll
            for (int mi = 0; mi < 4; mi++)
                #pragma unroll
                for (int ni = 0; ni < 4; ni++)
                    mma_bf16(c[mi][ni][0], c[mi][ni][1], c[mi][ni][2], c[mi][ni][3],
                             aL[mi][0], aL[mi][1], aL[mi][2], aL[mi][3],
                             bH[ni][0], bH[ni][1]);
        }
    }

    // ---- epilogue: bias + store (same fragment->C map as m16n8k8) ----
    #pragma unroll
    for (int ni = 0; ni < 4; ni++) {
        const int col = colBase + warp_n * 32 + ni * 8 + 2 * t;
        const float2 bb = *(const float2*)(bias + col);
        #pragma unroll
        for (int mi = 0; mi < 4; mi++) {
            const int row = rowBase + warp_m * 64 + mi * 16 + g;
            float2 o0, o1;
            o0.x = c[mi][ni][0] + bb.x;  o0.y = c[mi][ni][1] + bb.y;
            o1.x = c[mi][ni][2] + bb.x;  o1.y = c[mi][ni][3] + bb.y;
            *(float2*)(C + (size_t)row * N + col)       = o0;
            *(float2*)(C + (size_t)(row + 8) * N + col) = o1;
        }
    }
}

// ---------------- kernel 3: per-head LN (q,k) + RoPE + transpose ----------
__global__ __launch_bounds__(128) void qk_rope_kernel(
    const float* __restrict__ qkv,
    const float* __restrict__ q_scale, const float* __restrict__ k_scale,
    float* __restrict__ Q, float* __restrict__ K, float* __restrict__ V)
{
    const int w = blockIdx.x * 4 + (threadIdx.x >> 5);
    const int lane = threadIdx.x & 31;
    const int h = w % HH;
    const int s = (w / HH) % SS;
    const int b = w / (HH * SS);

    const float* row = qkv + (size_t)(b * SS + s) * (3 * DD) + h * HD;
    float q0 = row[lane],        q1 = row[lane + 32];
    float k0 = row[DD + lane],   k1 = row[DD + lane + 32];
    float v0 = row[2*DD + lane], v1 = row[2*DD + lane + 32];

    float mu = q0 + q1;
    #pragma unroll
    for (int o = 16; o; o >>= 1) mu += __shfl_xor_sync(0xffffffffu, mu, o);
    mu *= (1.f / 64.f);
    float a0 = q0 - mu, a1 = q1 - mu;
    float var = a0 * a0 + a1 * a1;
    #pragma unroll
    for (int o = 16; o; o >>= 1) var += __shfl_xor_sync(0xffffffffu, var, o);
    float r = rsqrtf(var * (1.f / 64.f) + EPS);
    float yq0 = a0 * r * q_scale[lane], yq1 = a1 * r * q_scale[lane + 32];

    mu = k0 + k1;
    #pragma unroll
    for (int o = 16; o; o >>= 1) mu += __shfl_xor_sync(0xffffffffu, mu, o);
    mu *= (1.f / 64.f);
    a0 = k0 - mu; a1 = k1 - mu;
    var = a0 * a0 + a1 * a1;
    #pragma unroll
    for (int o = 16; o; o >>= 1) var += __shfl_xor_sync(0xffffffffu, var, o);
    r = rsqrtf(var * (1.f / 64.f) + EPS);
    float yk0 = a0 * r * k_scale[lane], yk1 = a1 * r * k_scale[lane + 32];

    const float invf = (float)exp(-(double)(2 * lane) / 64.0 * log(10000.0));
    const float ang = (float)s * invf;
    const float c = cosf(ang), sn = sinf(ang);

    float oq0 = yq0 * c - yq1 * sn;
    float oq1 = yq1 * c + yq0 * sn;
    float ok0 = yk0 * c - yk1 * sn;
    float ok1 = yk1 * c + yk0 * sn;

    const size_t base = ((size_t)(b * HH + h) * SS + s) * HD;
    Q[base + lane] = oq0; Q[base + lane + 32] = oq1;
    K[base + lane] = ok0; K[base + lane + 32] = ok1;
    V[base + lane] = v0;  V[base + lane + 32] = v1;
}

// ---------------- kernel 4: flash attention v4 (EXACT R11, measured 850us) -
// tid=2m+h; h owns dims [32h,32h+32); 2 queries/thread; smem halves 144 B
// apart -> conflict-free. Scores for 8 keys per batch (shfl/ex2 latencies
// overlap), then PV. Scale folded into q registers.
__global__ __launch_bounds__(128, 2) void flash_kernel(
    const float* __restrict__ Q, const float* __restrict__ K,
    const float* __restrict__ V, float* __restrict__ O)
{
    __shared__ ulonglong2 Ks2[64 * 9 * 2];   // 64 keys * 18 ull2 (16 data + 2 pad)
    __shared__ ulonglong2 Vs2[64 * 9 * 2];

    const int tid = threadIdx.x;
    const int m = tid >> 1;
    const int h = tid & 1;
    const int bh = blockIdx.y;                 // 0..31
    const int q0 = blockIdx.x * 128;
    const int rA = q0 + m;
    const int rB = q0 + 64 + m;

    const float QSCALE = 0.125f * 1.44269504088896340736f;  // /sqrt(64) * log2(e)
    const u64 qsc = pack2(QSCALE, QSCALE);
    u64 qA[16], qB[16];
    {
        const ulonglong2* Qa = (const ulonglong2*)(Q + ((size_t)bh * SS + rA) * HD + h * 32);
        const ulonglong2* Qb = (const ulonglong2*)(Q + ((size_t)bh * SS + rB) * HD + h * 32);
        #pragma unroll
        for (int i = 0; i < 8; i++) {
            ulonglong2 ta = Qa[i];
            qA[2*i] = mul2(ta.x, qsc); qA[2*i+1] = mul2(ta.y, qsc);
            ulonglong2 tb = Qb[i];
            qB[2*i] = mul2(tb.x, qsc); qB[2*i+1] = mul2(tb.y, qsc);
        }
    }

    u64 accA[16], accB[16];
    #pragma unroll
    for (int i = 0; i < 16; i++) { accA[i] = 0ull; accB[i] = 0ull; }
    float la = 0.f, lb = 0.f;

    for (int kt = 0; kt < SS / 64; kt++) {
        const ulonglong2* Kg = (const ulonglong2*)(K + ((size_t)bh * SS + kt * 64) * HD);
        const ulonglong2* Vg = (const ulonglong2*)(V + ((size_t)bh * SS + kt * 64) * HD);
        __syncthreads();
        for (int e = tid; e < 1024; e += 128) {
            const int j  = e >> 4;
            const int qq = e & 15;
            const int di = j * 18 + (qq >> 3) * 9 + (qq & 7);
            Ks2[di] = Kg[e];
            Vs2[di] = Vg[e];
        }
        __syncthreads();

        const ulonglong2* Ksh = Ks2 + h * 9;
        const ulonglong2* Vsh = Vs2 + h * 9;

        #pragma unroll 1
        for (int jt = 0; jt < 64; jt += 8) {
            u64 cA[8], cB[8];
            #pragma unroll
            for (int j = 0; j < 8; j++) {
                const ulonglong2* kr = Ksh + (jt + j) * 18;
                u64 a = 0ull, b = 0ull;
                #pragma unroll
                for (int k4 = 0; k4 < 8; k4++) {
                    ulonglong2 kk = kr[k4];
                    a = fma2(qA[2*k4  ], kk.x, a);
                    a = fma2(qA[2*k4+1], kk.y, a);
                    b = fma2(qB[2*k4  ], kk.x, b);
                    b = fma2(qB[2*k4+1], kk.y, b);
                }
                cA[j] = a; cB[j] = b;
            }

            float pA[8], pB[8];
            #pragma unroll
            for (int j = 0; j < 8; j++) {
                float sa = lo2(cA[j]) + hi2(cA[j]);
                float sb = lo2(cB[j]) + hi2(cB[j]);
                sa += __shfl_xor_sync(0xffffffffu, sa, 1);
                sb += __shfl_xor_sync(0xffffffffu, sb, 1);
                pA[j] = ex2(sa);
                pB[j] = ex2(sb);
            }
            #pragma unroll
            for (int j = 0; j < 8; j++) { la += pA[j]; lb += pB[j]; }

            #pragma unroll
            for (int j = 0; j < 8; j++) {
                const ulonglong2* vr = Vsh + (jt + j) * 18;
                const u64 ppa = pack2(pA[j], pA[j]);
                const u64 ppb = pack2(pB[j], pB[j]);
                #pragma unroll
                for (int d4 = 0; d4 < 8; d4++) {
                    ulonglong2 vv = vr[d4];
                    accA[2*d4  ] = fma2(ppa, vv.x, accA[2*d4  ]);
                    accA[2*d4+1] = fma2(ppa, vv.y, accA[2*d4+1]);
                    accB[2*d4  ] = fma2(ppb, vv.x, accB[2*d4  ]);
                    accB[2*d4+1] = fma2(ppb, vv.y, accB[2*d4+1]);
                }
            }
        }
    }

    const int b = bh >> 4, hh = bh & 15;
    const u64 pia = pack2(1.f / la, 1.f / la);
    const u64 pib = pack2(1.f / lb, 1.f / lb);
    ulonglong2* Oa = (ulonglong2*)(O + ((size_t)(b * SS + rA)) * DD + hh * HD + h * 32);
    ulonglong2* Ob = (ulonglong2*)(O + ((size_t)(b * SS + rB)) * DD + hh * HD + h * 32);
    #pragma unroll
    for (int i = 0; i < 8; i++) {
        ulonglong2 ta, tb;
        ta.x = mul2(accA[2*i], pia); ta.y = mul2(accA[2*i+1], pia);
        tb.x = mul2(accB[2*i], pib); tb.y = mul2(accB[2*i+1], pib);
        Oa[i] = ta;
        Ob[i] = tb;
    }
}

// ---------------- launcher -------------------------------------------------
extern "C" void kernel_launch(void* const* d_in, const int* in_sizes, int n_in,
                              void* d_out, int out_size)
{
    const float* x        = (const float*)d_in[0];
    const float* w_qkv    = (const float*)d_in[1];
    const float* b_qkv    = (const float*)d_in[2];
    const float* w_out    = (const float*)d_in[3];
    const float* b_out    = (const float*)d_in[4];
    const float* ln_scale = (const float*)d_in[5];
    const float* ln_bias  = (const float*)d_in[6];
    const float* q_scale  = (const float*)d_in[7];
    const float* k_scale  = (const float*)d_in[8];
    float* out = (float*)d_out;

    float *xn, *qkv, *q, *k, *v, *attn;
    cudaGetSymbolAddress((void**)&xn,   g_xn);
    cudaGetSymbolAddress((void**)&qkv,  g_qkv);
    cudaGetSymbolAddress((void**)&q,    g_q);
    cudaGetSymbolAddress((void**)&k,    g_k);
    cudaGetSymbolAddress((void**)&v,    g_v);
    cudaGetSymbolAddress((void**)&attn, g_attn);

    // 1) input layernorm
    ln_kernel<<<ROWS, 256>>>(x, ln_scale, ln_bias, xn);

    // 2) QKV projection: [4096,1024] @ [1024,3072]  (3-pass bf16 mma)
    sgemm_bf16<<<dim3(3 * DD / 128, ROWS / 128), 256>>>(xn, w_qkv, b_qkv, qkv,
                                                        ROWS, 3 * DD, DD);

    // 3) head LN + RoPE + layout change
    qk_rope_kernel<<<(BB * SS * HH) / 4, 128>>>(qkv, q_scale, k_scale, q, k, v);

    // 4) attention (v4 exact: 128-query tiles, 2 queries/thread, f32x2)
    flash_kernel<<<dim3(SS / 128, BB * HH), 128>>>(q, k, v, attn);

    // 5) output projection: [4096,1024] @ [1024,1024]  (3-pass bf16 mma)
    sgemm_bf16<<<dim3(DD / 128, ROWS / 128), 256>>>(attn, w_out, b_out, out,
                                                    ROWS, DD, DD);
}